// round 4
// baseline (speedup 1.0000x reference)
#include <cuda_runtime.h>
#include <cuda_bf16.h>

#define Nn 100000
#define Ee 1600000
#define Dd 128
#define Hh 256
#define Ll 40
#define NB 98   // ceil(Nn / 1024)

// ---------------- scratch ------------------------------------------------------
__device__ int   g_degi[Nn];
__device__ int   g_offs[Nn + 1];
__device__ int   g_col[Ee];
__device__ int   g_part[NB];
__device__ int   g_base[NB];
__device__ float g_dinv[Nn];
__device__ float g_bufA[(size_t)Nn * Dd];
__device__ float g_bufB[(size_t)Nn * Dd];
__device__ float g_hid[(size_t)Nn * Hh];
// transposed bf16 hi/lo weights [N][K]:
//   W0,W1,W2: 128x128 ; Wm1: 256x128 ; Wm2: 64(pad from 40)x256
#define WT0 0
#define WT1 16384
#define WT2 32768
#define WTM1 49152
#define WTM2 81920
__device__ __nv_bfloat16 g_wtH[98304];
__device__ __nv_bfloat16 g_wtL[98304];

// ---------------- CSR build ----------------------------------------------------
__global__ void k_zero(int* __restrict__ a, int n) {
    int i = blockIdx.x * blockDim.x + threadIdx.x;
    if (i < n) a[i] = 0;
}

__global__ void k_bzero(__nv_bfloat16* __restrict__ a, __nv_bfloat16* __restrict__ b, int n) {
    int i = blockIdx.x * blockDim.x + threadIdx.x;
    if (i < n) { a[i] = __float2bfloat16(0.f); b[i] = __float2bfloat16(0.f); }
}

__global__ void k_count(const int* __restrict__ ei, int* __restrict__ degi, int e) {
    int i = blockIdx.x * blockDim.x + threadIdx.x;
    if (i < e) atomicAdd(&degi[ei[i]], 1);
}

__global__ void k_dinv(const int* __restrict__ degi, float* __restrict__ dinv, int n) {
    int i = blockIdx.x * blockDim.x + threadIdx.x;
    if (i < n) dinv[i] = rsqrtf((float)degi[i] + 1.0f);
}

__global__ void k_scanA(const int* __restrict__ degi, int* __restrict__ part) {
    __shared__ int s[1024];
    int i = blockIdx.x * 1024 + threadIdx.x;
    s[threadIdx.x] = (i < Nn) ? degi[i] : 0;
    __syncthreads();
    for (int d = 512; d > 0; d >>= 1) {
        if (threadIdx.x < d) s[threadIdx.x] += s[threadIdx.x + d];
        __syncthreads();
    }
    if (threadIdx.x == 0) part[blockIdx.x] = s[0];
}

__global__ void k_scanB(const int* __restrict__ part, int* __restrict__ base) {
    __shared__ int s[128];
    int t = threadIdx.x;
    int v = (t < NB) ? part[t] : 0;
    s[t] = v;
    __syncthreads();
    for (int d = 1; d < 128; d <<= 1) {
        int u = (t >= d) ? s[t - d] : 0;
        __syncthreads();
        s[t] += u;
        __syncthreads();
    }
    if (t < NB) base[t] = s[t] - v;
}

__global__ void k_scanC(const int* __restrict__ degi, const int* __restrict__ base,
                        int* __restrict__ offs) {
    __shared__ int s[1024];
    int t = threadIdx.x;
    int i = blockIdx.x * 1024 + t;
    int v = (i < Nn) ? degi[i] : 0;
    s[t] = v;
    __syncthreads();
    for (int d = 1; d < 1024; d <<= 1) {
        int u = (t >= d) ? s[t - d] : 0;
        __syncthreads();
        s[t] += u;
        __syncthreads();
    }
    int exc = s[t] - v + base[blockIdx.x];
    if (i < Nn) {
        offs[i] = exc;
        if (i == Nn - 1) offs[Nn] = exc + v;
    }
}

__global__ void k_fill(const int* __restrict__ ei, const int* __restrict__ offs,
                       int* __restrict__ degi, int* __restrict__ col, int e) {
    int i = blockIdx.x * blockDim.x + threadIdx.x;
    if (i < e) {
        int r = ei[i];
        int c = ei[e + i];
        int pos = offs[r] + atomicSub(&degi[r], 1) - 1;
        col[pos] = c;
    }
}

// ---------------- weight conversion: W[K][N] -> Wt hi/lo [N][K] ---------------
__global__ void k_wconv(const float* __restrict__ W, __nv_bfloat16* __restrict__ H,
                        __nv_bfloat16* __restrict__ L, int K, int N) {
    int i = blockIdx.x * blockDim.x + threadIdx.x;
    if (i < K * N) {
        int k = i / N, n = i % N;
        float w = W[i];
        __nv_bfloat16 h = __float2bfloat16(w);
        __nv_bfloat16 l = __float2bfloat16(w - __bfloat162float(h));
        H[(size_t)n * K + k] = h;
        L[(size_t)n * K + k] = l;
    }
}

// ---------------- prescale: xs = dinv[row] * x --------------------------------
__global__ void k_prescale(const float4* __restrict__ x, const float* __restrict__ dinv,
                           float4* __restrict__ xs) {
    int t = blockIdx.x * blockDim.x + threadIdx.x;
    if (t < Nn * 32) {
        float d = dinv[t >> 5];
        float4 v = x[t];
        v.x *= d; v.y *= d; v.z *= d; v.w *= d;
        xs[t] = v;
    }
}

// ---------------- aggregation: one warp per node, 4-way unrolled sum ----------
// src is prescaled (dinv[c]*x[c]); dst[r] = dinv[r] * (src[r] + sum_{c in N(r)} src[c])
__global__ void k_gather(const int* __restrict__ offs, const int* __restrict__ col,
                         const float* __restrict__ dinv, const float4* __restrict__ src,
                         float4* __restrict__ dst) {
    int w    = (int)((blockIdx.x * (size_t)blockDim.x + threadIdx.x) >> 5);
    int lane = threadIdx.x & 31;
    if (w >= Nn) return;

    float4 s0 = __ldg(&src[(size_t)w * 32 + lane]);   // self term
    float4 s1 = make_float4(0.f, 0.f, 0.f, 0.f);
    float4 s2 = make_float4(0.f, 0.f, 0.f, 0.f);
    float4 s3 = make_float4(0.f, 0.f, 0.f, 0.f);

    int beg = __ldg(&offs[w]), end = __ldg(&offs[w + 1]);
    int j = beg;
    for (; j + 4 <= end; j += 4) {
        int c0 = __ldg(&col[j]);
        int c1 = __ldg(&col[j + 1]);
        int c2 = __ldg(&col[j + 2]);
        int c3 = __ldg(&col[j + 3]);
        float4 v0 = __ldg(&src[(size_t)c0 * 32 + lane]);
        float4 v1 = __ldg(&src[(size_t)c1 * 32 + lane]);
        float4 v2 = __ldg(&src[(size_t)c2 * 32 + lane]);
        float4 v3 = __ldg(&src[(size_t)c3 * 32 + lane]);
        s0.x += v0.x; s0.y += v0.y; s0.z += v0.z; s0.w += v0.w;
        s1.x += v1.x; s1.y += v1.y; s1.z += v1.z; s1.w += v1.w;
        s2.x += v2.x; s2.y += v2.y; s2.z += v2.z; s2.w += v2.w;
        s3.x += v3.x; s3.y += v3.y; s3.z += v3.z; s3.w += v3.w;
    }
    for (; j < end; j++) {
        int c = __ldg(&col[j]);
        float4 v = __ldg(&src[(size_t)c * 32 + lane]);
        s0.x += v.x; s0.y += v.y; s0.z += v.z; s0.w += v.w;
    }
    float di = __ldg(&dinv[w]);
    float4 o;
    o.x = di * (s0.x + s1.x + s2.x + s3.x);
    o.y = di * (s0.y + s1.y + s2.y + s3.y);
    o.z = di * (s0.z + s1.z + s2.z + s3.z);
    o.w = di * (s0.w + s1.w + s2.w + s3.w);
    dst[(size_t)w * 32 + lane] = o;
}

// ---------------- split-bf16 tensor-core GEMM with ldmatrix -------------------
__device__ __forceinline__ void mma16816(float* c, const unsigned* a, unsigned b0, unsigned b1) {
    asm volatile(
        "mma.sync.aligned.m16n8k16.row.col.f32.bf16.bf16.f32 "
        "{%0,%1,%2,%3},{%4,%5,%6,%7},{%8,%9},{%0,%1,%2,%3};"
        : "+f"(c[0]), "+f"(c[1]), "+f"(c[2]), "+f"(c[3])
        : "r"(a[0]), "r"(a[1]), "r"(a[2]), "r"(a[3]), "r"(b0), "r"(b1));
}

__device__ __forceinline__ void ldsm4(unsigned addr, unsigned& r0, unsigned& r1,
                                      unsigned& r2, unsigned& r3) {
    asm volatile("ldmatrix.sync.aligned.m8n8.x4.shared.b16 {%0,%1,%2,%3}, [%4];"
                 : "=r"(r0), "=r"(r1), "=r"(r2), "=r"(r3) : "r"(addr));
}

// M tile = 64. out = (relu?)(A @ Wt^T + b) [* dinv per row if PRESCALE]
// A fp32 [nrows, KEL]; Wt hi/lo bf16 [*, KEL]; 8 warps = 2(M) x 4(N).
template<int KEL, int NTILE, int NVALID, bool RELU, bool PRESCALE>
__global__ void k_gemm_tc(const float* __restrict__ A,
                          const __nv_bfloat16* __restrict__ WtH,
                          const __nv_bfloat16* __restrict__ WtL,
                          const float* __restrict__ bias,
                          const float* __restrict__ dinv,
                          float* __restrict__ out, int nrows, int ldc) {
    constexpr int KSTR  = KEL + 8;
    constexpr int NT    = NTILE / 4;   // warp n-tile
    constexpr int NFRAG = NT / 8;
    constexpr int NPAIR = NT / 16;
    extern __shared__ __nv_bfloat16 smb[];
    __nv_bfloat16* AsH = smb;
    __nv_bfloat16* AsL = AsH + 64 * KSTR;
    __nv_bfloat16* WsH = AsL + 64 * KSTR;
    __nv_bfloat16* WsL = WsH + NTILE * KSTR;

    int tid = threadIdx.x;
    int m0 = blockIdx.x * 64;
    int n0 = blockIdx.y * NTILE;

    // stage A -> hi/lo bf16
    constexpr int C4 = KEL / 4;
#pragma unroll
    for (int it = 0; it < 64 * C4 / 256; it++) {
        int i = tid + 256 * it;
        int r = i / C4, c4 = i % C4;
        float4 v = (m0 + r < nrows) ? __ldg(&((const float4*)A)[(size_t)(m0 + r) * C4 + c4])
                                    : make_float4(0.f, 0.f, 0.f, 0.f);
        __nv_bfloat16 h0 = __float2bfloat16(v.x), h1 = __float2bfloat16(v.y);
        __nv_bfloat16 h2 = __float2bfloat16(v.z), h3 = __float2bfloat16(v.w);
        __nv_bfloat16 l0 = __float2bfloat16(v.x - __bfloat162float(h0));
        __nv_bfloat16 l1 = __float2bfloat16(v.y - __bfloat162float(h1));
        __nv_bfloat16 l2 = __float2bfloat16(v.z - __bfloat162float(h2));
        __nv_bfloat16 l3 = __float2bfloat16(v.w - __bfloat162float(h3));
        int o = r * KSTR + c4 * 4;
        *(__nv_bfloat162*)&AsH[o]     = __nv_bfloat162{h0, h1};
        *(__nv_bfloat162*)&AsH[o + 2] = __nv_bfloat162{h2, h3};
        *(__nv_bfloat162*)&AsL[o]     = __nv_bfloat162{l0, l1};
        *(__nv_bfloat162*)&AsL[o + 2] = __nv_bfloat162{l2, l3};
    }
    // stage W slice (rows n0..n0+NTILE-1), 16B chunks
    constexpr int C8 = KEL / 8;
#pragma unroll
    for (int it = 0; it < NTILE * C8 / 256; it++) {
        int i = tid + 256 * it;
        int r = i / C8, c = i % C8;
        *(uint4*)&WsH[r * KSTR + c * 8] = ((const uint4*)(WtH + (size_t)(n0 + r) * KEL))[c];
        *(uint4*)&WsL[r * KSTR + c * 8] = ((const uint4*)(WtL + (size_t)(n0 + r) * KEL))[c];
    }
    __syncthreads();

    int lane = tid & 31, wid = tid >> 5;
    int wm = (wid & 1) * 32;
    int wn = (wid >> 1) * NT;

    unsigned aOffH = (unsigned)__cvta_generic_to_shared(AsH) +
                     (((wm + (lane & 15)) * KSTR + (lane >> 4) * 8) << 1);
    unsigned aOffL = aOffH + 64 * KSTR * 2;
    unsigned bOffH = (unsigned)__cvta_generic_to_shared(WsH) +
                     (((wn + (lane & 7) + ((lane >> 4) & 1) * 8) * KSTR +
                       ((lane >> 3) & 1) * 8) << 1);
    unsigned bOffL = bOffH + NTILE * KSTR * 2;

    float acc[2][NFRAG][4];
#pragma unroll
    for (int mt = 0; mt < 2; mt++)
#pragma unroll
        for (int nf = 0; nf < NFRAG; nf++)
#pragma unroll
            for (int q = 0; q < 4; q++) acc[mt][nf][q] = 0.f;

#pragma unroll
    for (int ks = 0; ks < KEL / 16; ks++) {
        unsigned ko = ks * 32;
        unsigned aH[2][4], aL[2][4];
        ldsm4(aOffH + ko, aH[0][0], aH[0][1], aH[0][2], aH[0][3]);
        ldsm4(aOffH + 16 * KSTR * 2 + ko, aH[1][0], aH[1][1], aH[1][2], aH[1][3]);
        ldsm4(aOffL + ko, aL[0][0], aL[0][1], aL[0][2], aL[0][3]);
        ldsm4(aOffL + 16 * KSTR * 2 + ko, aL[1][0], aL[1][1], aL[1][2], aL[1][3]);
#pragma unroll
        for (int p = 0; p < NPAIR; p++) {
            unsigned bH[4], bL[4];
            ldsm4(bOffH + p * 16 * KSTR * 2 + ko, bH[0], bH[1], bH[2], bH[3]);
            ldsm4(bOffL + p * 16 * KSTR * 2 + ko, bL[0], bL[1], bL[2], bL[3]);
#pragma unroll
            for (int mt = 0; mt < 2; mt++) {
                mma16816(acc[mt][2 * p], aH[mt], bH[0], bH[1]);
                mma16816(acc[mt][2 * p], aH[mt], bL[0], bL[1]);
                mma16816(acc[mt][2 * p], aL[mt], bH[0], bH[1]);
                mma16816(acc[mt][2 * p + 1], aH[mt], bH[2], bH[3]);
                mma16816(acc[mt][2 * p + 1], aH[mt], bL[2], bL[3]);
                mma16816(acc[mt][2 * p + 1], aL[mt], bH[2], bH[3]);
            }
        }
    }

    // epilogue
    int g = lane >> 2, t = lane & 3;
#pragma unroll
    for (int nf = 0; nf < NFRAG; nf++) {
        int cg = n0 + wn + nf * 8 + 2 * t;
        bool cok = cg < NVALID;      // NVALID even, cg even -> covers cg+1 too
        float bv0 = cok ? bias[cg] : 0.f;
        float bv1 = cok ? bias[cg + 1] : 0.f;
#pragma unroll
        for (int mt = 0; mt < 2; mt++) {
            int r0 = m0 + wm + mt * 16 + g;
            float v0 = acc[mt][nf][0] + bv0, v1 = acc[mt][nf][1] + bv1;
            float v2 = acc[mt][nf][2] + bv0, v3 = acc[mt][nf][3] + bv1;
            if (RELU) {
                v0 = fmaxf(v0, 0.f); v1 = fmaxf(v1, 0.f);
                v2 = fmaxf(v2, 0.f); v3 = fmaxf(v3, 0.f);
            }
            if (PRESCALE) {
                float d0 = (r0 < nrows) ? dinv[r0] : 0.f;
                float d1 = (r0 + 8 < nrows) ? dinv[r0 + 8] : 0.f;
                v0 *= d0; v1 *= d0; v2 *= d1; v3 *= d1;
            }
            if (cok && r0 < nrows)
                *(float2*)&out[(size_t)r0 * ldc + cg] = make_float2(v0, v1);
            if (cok && r0 + 8 < nrows)
                *(float2*)&out[(size_t)(r0 + 8) * ldc + cg] = make_float2(v2, v3);
        }
    }
}

#define SMEM_L  ((64 + 64 + 128 + 128) * 136 * 2)   // 104448 (KEL=128, NTILE=128)
#define SMEM_M2 ((64 + 64 + 64 + 64) * 264 * 2)     // 135168 (KEL=256, NTILE=64)

extern "C" void kernel_launch(void* const* d_in, const int* in_sizes, int n_in,
                              void* d_out, int out_size) {
    const float* x   = (const float*)d_in[0];
    const int*   ei  = (const int*)  d_in[1];
    const float* W0  = (const float*)d_in[2];
    const float* b0  = (const float*)d_in[3];
    const float* W1  = (const float*)d_in[4];
    const float* b1  = (const float*)d_in[5];
    const float* W2  = (const float*)d_in[6];
    const float* b2  = (const float*)d_in[7];
    const float* Wm1 = (const float*)d_in[8];
    const float* bm1 = (const float*)d_in[9];
    const float* Wm2 = (const float*)d_in[10];
    const float* bm2 = (const float*)d_in[11];
    float* out = (float*)d_out;

    const int n = Nn, e = Ee;

    int *degi, *offs, *col, *part, *base;
    float *dinv, *bufA, *bufB, *hid;
    __nv_bfloat16 *wtH, *wtL;
    cudaGetSymbolAddress((void**)&degi, g_degi);
    cudaGetSymbolAddress((void**)&offs, g_offs);
    cudaGetSymbolAddress((void**)&col,  g_col);
    cudaGetSymbolAddress((void**)&part, g_part);
    cudaGetSymbolAddress((void**)&base, g_base);
    cudaGetSymbolAddress((void**)&dinv, g_dinv);
    cudaGetSymbolAddress((void**)&bufA, g_bufA);
    cudaGetSymbolAddress((void**)&bufB, g_bufB);
    cudaGetSymbolAddress((void**)&hid,  g_hid);
    cudaGetSymbolAddress((void**)&wtH,  g_wtH);
    cudaGetSymbolAddress((void**)&wtL,  g_wtL);

    cudaFuncSetAttribute(k_gemm_tc<128, 128, 128, true, true>,
                         cudaFuncAttributeMaxDynamicSharedMemorySize, SMEM_L);
    cudaFuncSetAttribute(k_gemm_tc<128, 128, 128, true, false>,
                         cudaFuncAttributeMaxDynamicSharedMemorySize, SMEM_L);
    cudaFuncSetAttribute(k_gemm_tc<128, 128, 256, true, false>,
                         cudaFuncAttributeMaxDynamicSharedMemorySize, SMEM_L);
    cudaFuncSetAttribute(k_gemm_tc<256, 64, 40, false, false>,
                         cudaFuncAttributeMaxDynamicSharedMemorySize, SMEM_M2);

    const int TB = 256;
    dim3 gN((n + TB - 1) / TB);
    dim3 gE((e + TB - 1) / TB);
    dim3 gNW(((size_t)n * 32 + TB - 1) / TB);   // n warps
    dim3 gPS(((size_t)n * 32 + TB - 1) / TB);
    dim3 gL((n + 63) / 64, 1);
    dim3 gM1((n + 63) / 64, 2);
    dim3 gM2((n + 63) / 64, 1);

    // ---- CSR build + normalization ----
    k_zero <<<gN, TB>>>(degi, n);
    k_count<<<gE, TB>>>(ei, degi, e);
    k_dinv <<<gN, TB>>>(degi, dinv, n);
    k_scanA<<<NB, 1024>>>(degi, part);
    k_scanB<<<1, 128>>>(part, base);
    k_scanC<<<NB, 1024>>>(degi, base, offs);
    k_fill <<<gE, TB>>>(ei, offs, degi, col, e);

    // ---- weight conversion ----
    k_bzero<<<(16384 + 255) / 256, 256>>>(wtH + WTM2, wtL + WTM2, 16384);
    k_wconv<<<(128 * 128 + 255) / 256, 256>>>(W0,  wtH + WT0,  wtL + WT0,  128, 128);
    k_wconv<<<(128 * 128 + 255) / 256, 256>>>(W1,  wtH + WT1,  wtL + WT1,  128, 128);
    k_wconv<<<(128 * 128 + 255) / 256, 256>>>(W2,  wtH + WT2,  wtL + WT2,  128, 128);
    k_wconv<<<(128 * 256 + 255) / 256, 256>>>(Wm1, wtH + WTM1, wtL + WTM1, 128, 256);
    k_wconv<<<(256 * 40 + 255) / 256, 256>>>(Wm2, wtH + WTM2, wtL + WTM2, 256, 40);

    // ---- layer 0: prescale x, gather, gemm (epilogue writes dinv*relu) ----
    k_prescale<<<gPS, TB>>>((const float4*)x, dinv, (float4*)bufB);
    k_gather<<<gNW, TB>>>(offs, col, dinv, (const float4*)bufB, (float4*)bufA);
    k_gemm_tc<128, 128, 128, true, true><<<gL, TB, SMEM_L>>>(
        bufA, wtH + WT0, wtL + WT0, b0, dinv, bufB, n, 128);

    // ---- layer 1 ----
    k_gather<<<gNW, TB>>>(offs, col, dinv, (const float4*)bufB, (float4*)bufA);
    k_gemm_tc<128, 128, 128, true, true><<<gL, TB, SMEM_L>>>(
        bufA, wtH + WT1, wtL + WT1, b1, dinv, bufB, n, 128);

    // ---- layer 2 (plain h3 out) ----
    k_gather<<<gNW, TB>>>(offs, col, dinv, (const float4*)bufB, (float4*)bufA);
    k_gemm_tc<128, 128, 128, true, false><<<gL, TB, SMEM_L>>>(
        bufA, wtH + WT2, wtL + WT2, b2, dinv, bufB, n, 128);

    // ---- MLP ----
    k_gemm_tc<128, 128, 256, true, false><<<gM1, TB, SMEM_L>>>(
        bufB, wtH + WTM1, wtL + WTM1, bm1, dinv, hid, n, 256);
    k_gemm_tc<256, 64, 40, false, false><<<gM2, TB, SMEM_M2>>>(
        hid, wtH + WTM2, wtL + WTM2, bm2, dinv, out, n, 40);
}

// round 5
// speedup vs baseline: 1.3869x; 1.3869x over previous
#include <cuda_runtime.h>
#include <cuda_bf16.h>

#define Nn 100000
#define Ee 1600000
#define Dd 128
#define Hh 256
#define Ll 40
#define NB 98   // ceil(Nn / 1024)

// ---------------- scratch ------------------------------------------------------
__device__ int   g_degi[Nn];
__device__ int   g_offs[Nn + 1];
__device__ int   g_col[Ee];
__device__ int   g_part[NB];
__device__ int   g_base[NB];
__device__ float g_dinv[Nn];
__device__ float g_bufA[(size_t)Nn * Dd];
__device__ float g_bufB[(size_t)Nn * Dd];
__device__ float g_hid[(size_t)Nn * Hh];
// transposed bf16 hi/lo weights [N][K]:
//   W0,W1,W2: 128x128 ; Wm1: 256x128 ; Wm2: 64(pad from 40)x256
#define WT0 0
#define WT1 16384
#define WT2 32768
#define WTM1 49152
#define WTM2 81920
__device__ __nv_bfloat16 g_wtH[98304];
__device__ __nv_bfloat16 g_wtL[98304];

// ---------------- CSR build ----------------------------------------------------
__global__ void k_zero(int* __restrict__ a, int n) {
    int i = blockIdx.x * blockDim.x + threadIdx.x;
    if (i < n) a[i] = 0;
}

__global__ void k_bzero(__nv_bfloat16* __restrict__ a, __nv_bfloat16* __restrict__ b, int n) {
    int i = blockIdx.x * blockDim.x + threadIdx.x;
    if (i < n) { a[i] = __float2bfloat16(0.f); b[i] = __float2bfloat16(0.f); }
}

__global__ void k_count(const int* __restrict__ ei, int* __restrict__ degi, int e) {
    int i = blockIdx.x * blockDim.x + threadIdx.x;
    if (i < e) atomicAdd(&degi[ei[i]], 1);
}

__global__ void k_dinv(const int* __restrict__ degi, float* __restrict__ dinv, int n) {
    int i = blockIdx.x * blockDim.x + threadIdx.x;
    if (i < n) dinv[i] = rsqrtf((float)degi[i] + 1.0f);
}

__global__ void k_scanA(const int* __restrict__ degi, int* __restrict__ part) {
    __shared__ int s[1024];
    int i = blockIdx.x * 1024 + threadIdx.x;
    s[threadIdx.x] = (i < Nn) ? degi[i] : 0;
    __syncthreads();
    for (int d = 512; d > 0; d >>= 1) {
        if (threadIdx.x < d) s[threadIdx.x] += s[threadIdx.x + d];
        __syncthreads();
    }
    if (threadIdx.x == 0) part[blockIdx.x] = s[0];
}

__global__ void k_scanB(const int* __restrict__ part, int* __restrict__ base) {
    __shared__ int s[128];
    int t = threadIdx.x;
    int v = (t < NB) ? part[t] : 0;
    s[t] = v;
    __syncthreads();
    for (int d = 1; d < 128; d <<= 1) {
        int u = (t >= d) ? s[t - d] : 0;
        __syncthreads();
        s[t] += u;
        __syncthreads();
    }
    if (t < NB) base[t] = s[t] - v;
}

__global__ void k_scanC(const int* __restrict__ degi, const int* __restrict__ base,
                        int* __restrict__ offs) {
    __shared__ int s[1024];
    int t = threadIdx.x;
    int i = blockIdx.x * 1024 + t;
    int v = (i < Nn) ? degi[i] : 0;
    s[t] = v;
    __syncthreads();
    for (int d = 1; d < 1024; d <<= 1) {
        int u = (t >= d) ? s[t - d] : 0;
        __syncthreads();
        s[t] += u;
        __syncthreads();
    }
    int exc = s[t] - v + base[blockIdx.x];
    if (i < Nn) {
        offs[i] = exc;
        if (i == Nn - 1) offs[Nn] = exc + v;
    }
}

__global__ void k_fill(const int* __restrict__ ei, const int* __restrict__ offs,
                       int* __restrict__ degi, int* __restrict__ col, int e) {
    int i = blockIdx.x * blockDim.x + threadIdx.x;
    if (i < e) {
        int r = ei[i];
        int c = ei[e + i];
        int pos = offs[r] + atomicSub(&degi[r], 1) - 1;
        col[pos] = c;
    }
}

// ---------------- weight conversion: W[K][N] -> Wt hi/lo [N][K] ---------------
__global__ void k_wconv(const float* __restrict__ W, __nv_bfloat16* __restrict__ H,
                        __nv_bfloat16* __restrict__ L, int K, int N) {
    int i = blockIdx.x * blockDim.x + threadIdx.x;
    if (i < K * N) {
        int k = i / N, n = i % N;
        float w = W[i];
        __nv_bfloat16 h = __float2bfloat16(w);
        __nv_bfloat16 l = __float2bfloat16(w - __bfloat162float(h));
        H[(size_t)n * K + k] = h;
        L[(size_t)n * K + k] = l;
    }
}

// ---------------- aggregation: one warp per node (R3 proven version) ----------
__global__ void k_gather(const int* __restrict__ offs, const int* __restrict__ col,
                         const float* __restrict__ dinv, const float4* __restrict__ src,
                         float4* __restrict__ dst) {
    int w    = (int)((blockIdx.x * (size_t)blockDim.x + threadIdx.x) >> 5);
    int lane = threadIdx.x & 31;
    if (w >= Nn) return;

    float di = __ldg(&dinv[w]);
    float4 acc = __ldg(&src[(size_t)w * 32 + lane]);
    acc.x *= di; acc.y *= di; acc.z *= di; acc.w *= di;

    int beg = __ldg(&offs[w]), end = __ldg(&offs[w + 1]);
    int c = (beg < end) ? __ldg(&col[beg]) : 0;
    for (int j = beg; j < end; j++) {
        int cn = (j + 1 < end) ? __ldg(&col[j + 1]) : 0;
        float wc = __ldg(&dinv[c]);
        float4 v = __ldg(&src[(size_t)c * 32 + lane]);
        acc.x = fmaf(wc, v.x, acc.x);
        acc.y = fmaf(wc, v.y, acc.y);
        acc.z = fmaf(wc, v.z, acc.z);
        acc.w = fmaf(wc, v.w, acc.w);
        c = cn;
    }
    acc.x *= di; acc.y *= di; acc.z *= di; acc.w *= di;
    dst[(size_t)w * 32 + lane] = acc;
}

// ---------------- bf16 split-precision tensor-core GEMM (R3 layout) -----------
// 128(M) x NTILE(N) block tile, 8 warps = 4(M) x 2(N); whole K resident.
__device__ __forceinline__ void mma16816(float* c, const unsigned* a, unsigned b0, unsigned b1) {
    asm volatile(
        "mma.sync.aligned.m16n8k16.row.col.f32.bf16.bf16.f32 "
        "{%0,%1,%2,%3},{%4,%5,%6,%7},{%8,%9},{%0,%1,%2,%3};"
        : "+f"(c[0]), "+f"(c[1]), "+f"(c[2]), "+f"(c[3])
        : "r"(a[0]), "r"(a[1]), "r"(a[2]), "r"(a[3]), "r"(b0), "r"(b1));
}

template<int KEL, int NTILE, int NVALID, bool RELU>
__global__ void k_gemm_tc(const float* __restrict__ A, const __nv_bfloat16* __restrict__ WtH,
                          const __nv_bfloat16* __restrict__ WtL, const float* __restrict__ bias,
                          float* __restrict__ out, int nrows, int ldc) {
    constexpr int KSTR  = KEL + 8;
    constexpr int NT    = NTILE / 2;   // warp n-extent
    constexpr int NFRAG = NT / 8;
    extern __shared__ __nv_bfloat16 smb[];
    __nv_bfloat16* AsH = smb;
    __nv_bfloat16* AsL = AsH + 128 * KSTR;
    __nv_bfloat16* WsH = AsL + 128 * KSTR;
    __nv_bfloat16* WsL = WsH + NTILE * KSTR;

    int tid = threadIdx.x;
    int m0 = blockIdx.x * 128;
    int n0 = blockIdx.y * NTILE;

    // stage A: fp32 -> bf16 hi/lo
    constexpr int C4 = KEL / 4;
#pragma unroll
    for (int it = 0; it < 128 * C4 / 256; it++) {
        int i = tid + 256 * it;
        int r = i / C4, c4 = i % C4;
        float4 v = (m0 + r < nrows) ? ((const float4*)A)[(size_t)(m0 + r) * C4 + c4]
                                    : make_float4(0.f, 0.f, 0.f, 0.f);
        __nv_bfloat16 h0 = __float2bfloat16(v.x), h1 = __float2bfloat16(v.y);
        __nv_bfloat16 h2 = __float2bfloat16(v.z), h3 = __float2bfloat16(v.w);
        __nv_bfloat16 l0 = __float2bfloat16(v.x - __bfloat162float(h0));
        __nv_bfloat16 l1 = __float2bfloat16(v.y - __bfloat162float(h1));
        __nv_bfloat16 l2 = __float2bfloat16(v.z - __bfloat162float(h2));
        __nv_bfloat16 l3 = __float2bfloat16(v.w - __bfloat162float(h3));
        int o = r * KSTR + c4 * 4;
        *(__nv_bfloat162*)&AsH[o]     = __nv_bfloat162{h0, h1};
        *(__nv_bfloat162*)&AsH[o + 2] = __nv_bfloat162{h2, h3};
        *(__nv_bfloat162*)&AsL[o]     = __nv_bfloat162{l0, l1};
        *(__nv_bfloat162*)&AsL[o + 2] = __nv_bfloat162{l2, l3};
    }
    // stage Wt slice (rows n0..n0+NTILE-1), 16B chunks
    constexpr int C8 = KEL / 8;
    {
        const uint4* GH = (const uint4*)(WtH + (size_t)n0 * KEL);
        const uint4* GL = (const uint4*)(WtL + (size_t)n0 * KEL);
#pragma unroll
        for (int it = 0; it < NTILE * C8 / 256; it++) {
            int i = tid + 256 * it;
            int r = i / C8, c = i % C8;
            *(uint4*)((char*)WsH + r * (KSTR * 2) + c * 16) = GH[r * C8 + c];
            *(uint4*)((char*)WsL + r * (KSTR * 2) + c * 16) = GL[r * C8 + c];
        }
    }
    __syncthreads();

    int lane = tid & 31, wid = tid >> 5;
    int wm = (wid & 3) * 32;
    int wn = (wid >> 2) * NT;
    int g = lane >> 2, t = lane & 3;

    float acc[2][NFRAG][4];
#pragma unroll
    for (int mt = 0; mt < 2; mt++)
#pragma unroll
        for (int nt = 0; nt < NFRAG; nt++)
#pragma unroll
            for (int q = 0; q < 4; q++) acc[mt][nt][q] = 0.f;

#pragma unroll
    for (int ks = 0; ks < KEL / 16; ks++) {
        int k0 = ks * 16;
        unsigned aH[2][4], aL[2][4];
#pragma unroll
        for (int mt = 0; mt < 2; mt++) {
            int r = wm + mt * 16;
            aH[mt][0] = *(const unsigned*)&AsH[(r + g) * KSTR + k0 + 2 * t];
            aH[mt][1] = *(const unsigned*)&AsH[(r + g + 8) * KSTR + k0 + 2 * t];
            aH[mt][2] = *(const unsigned*)&AsH[(r + g) * KSTR + k0 + 8 + 2 * t];
            aH[mt][3] = *(const unsigned*)&AsH[(r + g + 8) * KSTR + k0 + 8 + 2 * t];
            aL[mt][0] = *(const unsigned*)&AsL[(r + g) * KSTR + k0 + 2 * t];
            aL[mt][1] = *(const unsigned*)&AsL[(r + g + 8) * KSTR + k0 + 2 * t];
            aL[mt][2] = *(const unsigned*)&AsL[(r + g) * KSTR + k0 + 8 + 2 * t];
            aL[mt][3] = *(const unsigned*)&AsL[(r + g + 8) * KSTR + k0 + 8 + 2 * t];
        }
#pragma unroll
        for (int nt = 0; nt < NFRAG; nt++) {
            int nn = wn + nt * 8 + g;
            unsigned bH0 = *(const unsigned*)&WsH[nn * KSTR + k0 + 2 * t];
            unsigned bH1 = *(const unsigned*)&WsH[nn * KSTR + k0 + 8 + 2 * t];
            unsigned bL0 = *(const unsigned*)&WsL[nn * KSTR + k0 + 2 * t];
            unsigned bL1 = *(const unsigned*)&WsL[nn * KSTR + k0 + 8 + 2 * t];
#pragma unroll
            for (int mt = 0; mt < 2; mt++) {
                mma16816(acc[mt][nt], aH[mt], bH0, bH1);
                mma16816(acc[mt][nt], aH[mt], bL0, bL1);
                mma16816(acc[mt][nt], aL[mt], bH0, bH1);
            }
        }
    }

    // epilogue
#pragma unroll
    for (int nt = 0; nt < NFRAG; nt++) {
        int cg = n0 + wn + nt * 8 + 2 * t;
        bool cok = cg < NVALID;        // NVALID even, cg even -> covers cg+1
        float bv0 = cok ? bias[cg] : 0.f;
        float bv1 = cok ? bias[cg + 1] : 0.f;
#pragma unroll
        for (int mt = 0; mt < 2; mt++) {
            int r0 = m0 + wm + mt * 16 + g;
            float v0 = acc[mt][nt][0] + bv0, v1 = acc[mt][nt][1] + bv1;
            float v2 = acc[mt][nt][2] + bv0, v3 = acc[mt][nt][3] + bv1;
            if (RELU) {
                v0 = fmaxf(v0, 0.f); v1 = fmaxf(v1, 0.f);
                v2 = fmaxf(v2, 0.f); v3 = fmaxf(v3, 0.f);
            }
            if (cok && r0 < nrows) {
                out[(size_t)r0 * ldc + cg]     = v0;
                out[(size_t)r0 * ldc + cg + 1] = v1;
            }
            if (cok && r0 + 8 < nrows) {
                out[(size_t)(r0 + 8) * ldc + cg]     = v2;
                out[(size_t)(r0 + 8) * ldc + cg + 1] = v3;
            }
        }
    }
}

#define SMEM_TC  (4 * 128 * 136 * 2)               // 139264 (KEL=128, NTILE=128)
#define SMEM_M2  ((2 * 128 + 2 * 64) * 264 * 2)    // 202752 (KEL=256, NTILE=64)

extern "C" void kernel_launch(void* const* d_in, const int* in_sizes, int n_in,
                              void* d_out, int out_size) {
    const float* x   = (const float*)d_in[0];
    const int*   ei  = (const int*)  d_in[1];
    const float* W0  = (const float*)d_in[2];
    const float* b0  = (const float*)d_in[3];
    const float* W1  = (const float*)d_in[4];
    const float* b1  = (const float*)d_in[5];
    const float* W2  = (const float*)d_in[6];
    const float* b2  = (const float*)d_in[7];
    const float* Wm1 = (const float*)d_in[8];
    const float* bm1 = (const float*)d_in[9];
    const float* Wm2 = (const float*)d_in[10];
    const float* bm2 = (const float*)d_in[11];
    float* out = (float*)d_out;

    const int n = Nn, e = Ee;

    int *degi, *offs, *col, *part, *base;
    float *dinv, *bufA, *bufB, *hid;
    __nv_bfloat16 *wtH, *wtL;
    cudaGetSymbolAddress((void**)&degi, g_degi);
    cudaGetSymbolAddress((void**)&offs, g_offs);
    cudaGetSymbolAddress((void**)&col,  g_col);
    cudaGetSymbolAddress((void**)&part, g_part);
    cudaGetSymbolAddress((void**)&base, g_base);
    cudaGetSymbolAddress((void**)&dinv, g_dinv);
    cudaGetSymbolAddress((void**)&bufA, g_bufA);
    cudaGetSymbolAddress((void**)&bufB, g_bufB);
    cudaGetSymbolAddress((void**)&hid,  g_hid);
    cudaGetSymbolAddress((void**)&wtH,  g_wtH);
    cudaGetSymbolAddress((void**)&wtL,  g_wtL);

    cudaFuncSetAttribute(k_gemm_tc<128, 128, 128, true>,
                         cudaFuncAttributeMaxDynamicSharedMemorySize, SMEM_TC);
    cudaFuncSetAttribute(k_gemm_tc<128, 128, 256, true>,
                         cudaFuncAttributeMaxDynamicSharedMemorySize, SMEM_TC);
    cudaFuncSetAttribute(k_gemm_tc<256, 64, 40, false>,
                         cudaFuncAttributeMaxDynamicSharedMemorySize, SMEM_M2);

    const int TB = 256;
    dim3 gN((n + TB - 1) / TB);
    dim3 gE((e + TB - 1) / TB);
    dim3 gNW(((size_t)n * 32 + TB - 1) / TB);
    dim3 gTC((n + 127) / 128, 1);
    dim3 gTC2((n + 127) / 128, 2);

    // ---- CSR build + normalization ----
    k_zero <<<gN, TB>>>(degi, n);
    k_count<<<gE, TB>>>(ei, degi, e);
    k_dinv <<<gN, TB>>>(degi, dinv, n);
    k_scanA<<<NB, 1024>>>(degi, part);
    k_scanB<<<1, 128>>>(part, base);
    k_scanC<<<NB, 1024>>>(degi, base, offs);
    k_fill <<<gE, TB>>>(ei, offs, degi, col, e);

    // ---- weight conversion (transposed bf16 hi/lo; Wm2 zero-padded to 64) ----
    k_bzero<<<(16384 + 255) / 256, 256>>>(wtH + WTM2, wtL + WTM2, 16384);
    k_wconv<<<(128 * 128 + 255) / 256, 256>>>(W0,  wtH + WT0,  wtL + WT0,  128, 128);
    k_wconv<<<(128 * 128 + 255) / 256, 256>>>(W1,  wtH + WT1,  wtL + WT1,  128, 128);
    k_wconv<<<(128 * 128 + 255) / 256, 256>>>(W2,  wtH + WT2,  wtL + WT2,  128, 128);
    k_wconv<<<(128 * 256 + 255) / 256, 256>>>(Wm1, wtH + WTM1, wtL + WTM1, 128, 256);
    k_wconv<<<(256 * 40 + 255) / 256, 256>>>(Wm2, wtH + WTM2, wtL + WTM2, 256, 40);

    // ---- layer 0 ----
    k_gather<<<gNW, TB>>>(offs, col, dinv, (const float4*)x, (float4*)bufA);
    k_gemm_tc<128, 128, 128, true><<<gTC, TB, SMEM_TC>>>(bufA, wtH + WT0, wtL + WT0, b0, bufB, n, 128);
    // ---- layer 1 ----
    k_gather<<<gNW, TB>>>(offs, col, dinv, (const float4*)bufB, (float4*)bufA);
    k_gemm_tc<128, 128, 128, true><<<gTC, TB, SMEM_TC>>>(bufA, wtH + WT1, wtL + WT1, b1, bufB, n, 128);
    // ---- layer 2 ----
    k_gather<<<gNW, TB>>>(offs, col, dinv, (const float4*)bufB, (float4*)bufA);
    k_gemm_tc<128, 128, 128, true><<<gTC, TB, SMEM_TC>>>(bufA, wtH + WT2, wtL + WT2, b2, bufB, n, 128);

    // ---- MLP ----
    k_gemm_tc<128, 128, 256, true><<<gTC2, TB, SMEM_TC>>>(bufB, wtH + WTM1, wtL + WTM1, bm1, hid, n, 256);
    k_gemm_tc<256, 64, 40, false><<<gTC, TB, SMEM_M2>>>(hid, wtH + WTM2, wtL + WTM2, bm2, out, n, 40);
}